// round 1
// baseline (speedup 1.0000x reference)
#include <cuda_runtime.h>
#include <math.h>

#define B_   1024
#define T_   64
#define D_   512
#define H_   512
#define N4H  2048   // 4*H

// Scratch (device globals: allocation-free per harness rules)
__device__ float g_zx[(size_t)B_ * T_ * N4H];  // 512 MB: x@W + bias for all steps
__device__ float g_z [(size_t)B_ * N4H];       // 8 MB: per-step gate pre-activations
__device__ float g_h [B_ * H_];                // hidden state
__device__ float g_c [B_ * H_];                // cell state

// ---------------------------------------------------------------------------
// Zero h and c
// ---------------------------------------------------------------------------
__global__ void init_state_kernel(float* __restrict__ h, float* __restrict__ c) {
    int idx = blockIdx.x * blockDim.x + threadIdx.x;
    if (idx < B_ * H_) { h[idx] = 0.0f; c[idx] = 0.0f; }
}

// ---------------------------------------------------------------------------
// Tiled SGEMM: C[M,N] = A[M,K] @ Bm[K,N] (+ Cadd[m*ldadd+n]) (+ bias[n])
// BM=BN=128, BK=16, 256 threads, 8x8 per-thread microtile.
// Requires M%128==0, N%128==0, K%16==0 (true for all our shapes).
// ---------------------------------------------------------------------------
__global__ void __launch_bounds__(256)
sgemm_kernel(const float* __restrict__ A, int lda,
             const float* __restrict__ Bm, int ldb,
             float* __restrict__ C, int ldc,
             const float* __restrict__ Cadd, int ldadd,   // nullable
             const float* __restrict__ bias,              // nullable
             int M, int N, int K)
{
    __shared__ float As[16][128];
    __shared__ float Bs[16][128];

    const int tid = threadIdx.x;
    const int tx  = tid & 15;        // 0..15 (col group)
    const int ty  = tid >> 4;        // 0..15 (row group)
    const int row0 = blockIdx.y * 128;
    const int col0 = blockIdx.x * 128;

    float acc[8][8];
    #pragma unroll
    for (int i = 0; i < 8; i++)
        #pragma unroll
        for (int j = 0; j < 8; j++) acc[i][j] = 0.0f;

    for (int k0 = 0; k0 < K; k0 += 16) {
        // Load A tile (128 rows x 16 k) and B tile (16 k x 128 cols), float4.
        #pragma unroll
        for (int i = 0; i < 2; i++) {
            int v = tid + i * 256;
            // A: 512 float4 total; each row has 4 float4 along k
            int ar = v >> 2;             // 0..127
            int ak = (v & 3) * 4;        // 0,4,8,12
            float4 av = *reinterpret_cast<const float4*>(
                &A[(size_t)(row0 + ar) * lda + k0 + ak]);
            As[ak + 0][ar] = av.x;
            As[ak + 1][ar] = av.y;
            As[ak + 2][ar] = av.z;
            As[ak + 3][ar] = av.w;
            // B: 512 float4 total; each k-row has 32 float4 along n
            int bk = v >> 5;             // 0..15
            int bc = (v & 31) * 4;       // 0..124
            *reinterpret_cast<float4*>(&Bs[bk][bc]) =
                *reinterpret_cast<const float4*>(
                    &Bm[(size_t)(k0 + bk) * ldb + col0 + bc]);
        }
        __syncthreads();

        #pragma unroll
        for (int kk = 0; kk < 16; kk++) {
            float a[8], b[8];
            float4 a0 = *reinterpret_cast<const float4*>(&As[kk][ty * 8]);
            float4 a1 = *reinterpret_cast<const float4*>(&As[kk][ty * 8 + 4]);
            float4 b0 = *reinterpret_cast<const float4*>(&Bs[kk][tx * 8]);
            float4 b1 = *reinterpret_cast<const float4*>(&Bs[kk][tx * 8 + 4]);
            a[0]=a0.x; a[1]=a0.y; a[2]=a0.z; a[3]=a0.w;
            a[4]=a1.x; a[5]=a1.y; a[6]=a1.z; a[7]=a1.w;
            b[0]=b0.x; b[1]=b0.y; b[2]=b0.z; b[3]=b0.w;
            b[4]=b1.x; b[5]=b1.y; b[6]=b1.z; b[7]=b1.w;
            #pragma unroll
            for (int i = 0; i < 8; i++)
                #pragma unroll
                for (int j = 0; j < 8; j++)
                    acc[i][j] = fmaf(a[i], b[j], acc[i][j]);
        }
        __syncthreads();
    }

    // Epilogue
    #pragma unroll
    for (int i = 0; i < 8; i++) {
        int r = row0 + ty * 8 + i;
        #pragma unroll
        for (int j = 0; j < 8; j += 4) {
            int cidx = col0 + tx * 8 + j;
            float4 v;
            v.x = acc[i][j + 0]; v.y = acc[i][j + 1];
            v.z = acc[i][j + 2]; v.w = acc[i][j + 3];
            if (Cadd) {
                float4 w = *reinterpret_cast<const float4*>(
                    &Cadd[(size_t)r * ldadd + cidx]);
                v.x += w.x; v.y += w.y; v.z += w.z; v.w += w.w;
            }
            if (bias) {
                float4 w = *reinterpret_cast<const float4*>(&bias[cidx]);
                v.x += w.x; v.y += w.y; v.z += w.z; v.w += w.w;
            }
            *reinterpret_cast<float4*>(&C[(size_t)r * ldc + cidx]) = v;
        }
    }
}

// ---------------------------------------------------------------------------
// LSTM gate / state update for one timestep.
// z layout per row b: [i(0:H) | f(H:2H) | g(2H:3H) | o(3H:4H)]
// out[b, t, j] = h_new
// ---------------------------------------------------------------------------
__device__ __forceinline__ float sigmoidf_(float x) {
    return 1.0f / (1.0f + expf(-x));
}

__global__ void lstm_gate_kernel(const float* __restrict__ z,
                                 float* __restrict__ h,
                                 float* __restrict__ c,
                                 float* __restrict__ out,
                                 int t)
{
    int idx = blockIdx.x * blockDim.x + threadIdx.x;
    if (idx >= B_ * H_) return;
    int b = idx >> 9;          // / H_
    int j = idx & (H_ - 1);    // % H_

    const float* zr = z + (size_t)b * N4H;
    float zi = zr[j];
    float zf = zr[H_ + j];
    float zg = zr[2 * H_ + j];
    float zo = zr[3 * H_ + j];

    float ig = sigmoidf_(zi);
    float fg = sigmoidf_(zf);
    float gg = tanhf(zg);
    float og = sigmoidf_(zo);

    float c_new = fg * c[idx] + ig * gg;
    float h_new = og * tanhf(c_new);

    c[idx] = c_new;
    h[idx] = h_new;
    out[(size_t)b * T_ * H_ + (size_t)t * H_ + j] = h_new;
}

// ---------------------------------------------------------------------------
// Launch
// ---------------------------------------------------------------------------
extern "C" void kernel_launch(void* const* d_in, const int* in_sizes, int n_in,
                              void* d_out, int out_size)
{
    const float* x    = (const float*)d_in[0];  // [B, T, D]
    const float* W    = (const float*)d_in[1];  // [D, 4H]
    const float* U    = (const float*)d_in[2];  // [H, 4H]
    const float* bias = (const float*)d_in[3];  // [4H]
    float* out = (float*)d_out;                 // [B, T, H]

    float *zx, *z, *h, *c;
    cudaGetSymbolAddress((void**)&zx, g_zx);
    cudaGetSymbolAddress((void**)&z,  g_z);
    cudaGetSymbolAddress((void**)&h,  g_h);
    cudaGetSymbolAddress((void**)&c,  g_c);

    // Zero state
    init_state_kernel<<<(B_ * H_ + 255) / 256, 256>>>(h, c);

    // Precompute Zx = X @ W + bias for ALL timesteps in one big GEMM.
    // X viewed as (B*T, D) row-major; row m = b*T + t.
    {
        dim3 grid(N4H / 128, (B_ * T_) / 128);
        sgemm_kernel<<<grid, 256>>>(x, D_, W, N4H, zx, N4H,
                                    nullptr, 0, bias,
                                    B_ * T_, N4H, D_);
    }

    // Sequential recurrence
    dim3 rgrid(N4H / 128, B_ / 128);
    int gate_blocks = (B_ * H_ + 255) / 256;
    for (int t = 0; t < T_; t++) {
        // Z = h @ U + Zx[:, t, :]   (Zx row stride between b's is T*4H)
        sgemm_kernel<<<rgrid, 256>>>(h, H_, U, N4H, z, N4H,
                                     zx + (size_t)t * N4H, T_ * N4H,
                                     nullptr,
                                     B_, N4H, H_);
        lstm_gate_kernel<<<gate_blocks, 256>>>(z, h, c, out, t);
    }
}

// round 6
// speedup vs baseline: 2.8023x; 2.8023x over previous
#include <cuda_runtime.h>
#include <math.h>
#include <stdint.h>

#define B_   1024
#define T_   64
#define D_   512
#define H_   512
#define N4H  2048   // 4*H

// ---------------------------------------------------------------------------
// Scratch (device globals: allocation-free per harness rules)
// ---------------------------------------------------------------------------
__device__ float g_zx[(size_t)B_ * T_ * N4H];  // x@W + bias (gate-interleaved cols)
__device__ float g_h [B_ * H_];                // hidden state
__device__ float g_c [B_ * H_];                // cell state
__device__ float g_wt[(size_t)N4H * D_];       // W^T, gate-interleaved rows [2048,512]
__device__ float g_ut[(size_t)N4H * H_];       // U^T, gate-interleaved rows [2048,512]

// ---------------------------------------------------------------------------
// cp.async helpers
// ---------------------------------------------------------------------------
__device__ __forceinline__ uint32_t smem_u32(const void* p) {
    uint32_t a;
    asm("{ .reg .u64 t; cvta.to.shared.u64 t, %1; cvt.u32.u64 %0, t; }"
        : "=r"(a) : "l"(p));
    return a;
}
#define CP_ASYNC16(dst, src) \
    asm volatile("cp.async.cg.shared.global [%0], [%1], 16;" \
                 :: "r"(dst), "l"(src) : "memory")
#define CP_COMMIT() asm volatile("cp.async.commit_group;" ::: "memory")
#define CP_WAIT1()  asm volatile("cp.async.wait_group 1;" ::: "memory")
#define CP_WAIT0()  asm volatile("cp.async.wait_group 0;" ::: "memory")

__device__ __forceinline__ float tanh_fast(float x) {
    float y;
    asm("tanh.approx.f32 %0, %1;" : "=f"(y) : "f"(x));
    return y;
}
__device__ __forceinline__ float sig_fast(float x) {
    return 0.5f * tanh_fast(0.5f * x) + 0.5f;
}

// ---------------------------------------------------------------------------
// mma.sync m16n8k8 tf32 (fp32 bits passed through; HW truncates to tf32)
// ---------------------------------------------------------------------------
__device__ __forceinline__ void mma_tf32(float* c, const uint32_t* a,
                                         const uint32_t* b) {
    asm volatile(
        "mma.sync.aligned.m16n8k8.row.col.f32.tf32.tf32.f32 "
        "{%0,%1,%2,%3}, {%4,%5,%6,%7}, {%8,%9}, {%0,%1,%2,%3};"
        : "+f"(c[0]), "+f"(c[1]), "+f"(c[2]), "+f"(c[3])
        : "r"(a[0]), "r"(a[1]), "r"(a[2]), "r"(a[3]), "r"(b[0]), "r"(b[1]));
}

// ---------------------------------------------------------------------------
// Shared tile geometry. A/B K-chunk tiles: 128 rows x 32 k, stride 36 floats.
// Buffers (floats): A0 @0, B0 @4608, A1 @9216, B1 @13824. Total 18432 floats.
// Ztile (recurrent epilogue) overlays at 0 with stride 132 (128x132=16896).
// ---------------------------------------------------------------------------
#define SM_FLOATS 18432
#define SM_BYTES  (SM_FLOATS * 4)
#define TS 36    // tile row stride (floats)
#define ZS 132   // Ztile row stride (floats)

struct Frag { float acc[2][8][4]; };

// Load one K-chunk (A 128x32 from A[row0..][k0..], B 128x32 from BT[col0..][k0..])
__device__ __forceinline__ void load_chunk(float* sm, int buf,
                                           const float* A, int lda, int row0,
                                           const float* BT, int ldb, int col0,
                                           int k0, int tid) {
    uint32_t sa = smem_u32(sm + (buf ? 9216 : 0));
    uint32_t sbp = smem_u32(sm + (buf ? 13824 : 4608));
    #pragma unroll
    for (int i = 0; i < 4; i++) {
        int idx = tid + i * 256;          // 0..1023
        int r = idx >> 3, f = idx & 7;
        CP_ASYNC16(sa + (r * TS + f * 4) * 4,
                   &A[(size_t)(row0 + r) * lda + k0 + f * 4]);
        CP_ASYNC16(sbp + (r * TS + f * 4) * 4,
                   &BT[(size_t)(col0 + r) * ldb + k0 + f * 4]);
    }
}

// Compute one K-chunk (4 k8 steps, 16 mma each) from buffer `buf`.
__device__ __forceinline__ void compute_chunk(const float* sm, int buf,
                                              int m0w, int n0w, int lane,
                                              Frag& fr) {
    const float* As = sm + (buf ? 9216 : 0);
    const float* Bs = sm + (buf ? 13824 : 4608);
    const int q = lane & 3, p = lane >> 2;
    #pragma unroll
    for (int kk = 0; kk < 4; kk++) {
        const int kb = kk * 8;
        uint32_t a[2][4], b[8][2];
        #pragma unroll
        for (int mt = 0; mt < 2; mt++) {
            const float* ap = As + (m0w + mt * 16 + p) * TS + kb + q;
            a[mt][0] = __float_as_uint(ap[0]);
            a[mt][1] = __float_as_uint(ap[8 * TS]);
            a[mt][2] = __float_as_uint(ap[4]);
            a[mt][3] = __float_as_uint(ap[8 * TS + 4]);
        }
        #pragma unroll
        for (int nt = 0; nt < 8; nt++) {
            const float* bp = Bs + (n0w + nt * 8 + p) * TS + kb + q;
            b[nt][0] = __float_as_uint(bp[0]);
            b[nt][1] = __float_as_uint(bp[4]);
        }
        #pragma unroll
        for (int mt = 0; mt < 2; mt++)
            #pragma unroll
            for (int nt = 0; nt < 8; nt++)
                mma_tf32(fr.acc[mt][nt], a[mt], b[nt]);
    }
}

// ---------------------------------------------------------------------------
// Big GEMM: C[M,N] = A[M,K=512] @ BT[N,K]^T + bias   (plain epilogue)
// grid: (N/128, M/128), 256 threads.
// ---------------------------------------------------------------------------
__global__ void __launch_bounds__(256, 2)
gemm_bias_kernel(const float* __restrict__ A, int lda,
                 const float* __restrict__ BT, int ldb,
                 float* __restrict__ C, int ldc,
                 const float* __restrict__ bias)
{
    extern __shared__ float sm[];
    const int tid = threadIdx.x;
    const int wid = tid >> 5, lane = tid & 31;
    const int row0 = blockIdx.y * 128, col0 = blockIdx.x * 128;
    const int m0w = (wid & 3) * 32, n0w = (wid >> 2) * 64;

    Frag fr;
    #pragma unroll
    for (int mt = 0; mt < 2; mt++)
        #pragma unroll
        for (int nt = 0; nt < 8; nt++)
            #pragma unroll
            for (int j = 0; j < 4; j++) fr.acc[mt][nt][j] = 0.0f;

    load_chunk(sm, 0, A, lda, row0, BT, ldb, col0, 0, tid);
    CP_COMMIT();
    const int NC = 512 / 32;
    for (int i = 0; i < NC; i++) {
        if (i + 1 < NC) {
            load_chunk(sm, (i + 1) & 1, A, lda, row0, BT, ldb, col0,
                       (i + 1) * 32, tid);
            CP_COMMIT();
            CP_WAIT1();
        } else {
            CP_WAIT0();
        }
        __syncthreads();
        compute_chunk(sm, i & 1, m0w, n0w, lane, fr);
        __syncthreads();
    }

    // Epilogue: float2 stores + bias
    const int q = lane & 3, p = lane >> 2;
    #pragma unroll
    for (int mt = 0; mt < 2; mt++) {
        #pragma unroll
        for (int nt = 0; nt < 8; nt++) {
            int col = col0 + n0w + nt * 8 + 2 * q;
            float2 bb = *reinterpret_cast<const float2*>(&bias[col]);
            int r0 = row0 + m0w + mt * 16 + p;
            float2 v0 = {fr.acc[mt][nt][0] + bb.x, fr.acc[mt][nt][1] + bb.y};
            float2 v1 = {fr.acc[mt][nt][2] + bb.x, fr.acc[mt][nt][3] + bb.y};
            *reinterpret_cast<float2*>(&C[(size_t)r0 * ldc + col]) = v0;
            *reinterpret_cast<float2*>(&C[(size_t)(r0 + 8) * ldc + col]) = v1;
        }
    }
}

// ---------------------------------------------------------------------------
// Recurrent fused GEMM+LSTM step:
//   Ztile = h @ UT^T (128x128 tile of [B, 4H]); z += zx[b, t, :]
//   gates interleaved: cols 4g..4g+3 = (i, f, g, o) of hidden unit (col0/4 + g)
//   c_new = sig(f)*c + sig(i)*tanh(g);  h_new = sig(o)*tanh(c_new)
// grid: (N4H/128=16, B/128=8), 256 threads.
// ---------------------------------------------------------------------------
__global__ void __launch_bounds__(256, 2)
lstm_step_kernel(const float* __restrict__ h_in, const float* __restrict__ UT,
                 const float* __restrict__ zx, int t,
                 float* __restrict__ h_out, float* __restrict__ c,
                 float* __restrict__ out)
{
    extern __shared__ float sm[];
    const int tid = threadIdx.x;
    const int wid = tid >> 5, lane = tid & 31;
    const int row0 = blockIdx.y * 128, col0 = blockIdx.x * 128;
    const int m0w = (wid & 3) * 32, n0w = (wid >> 2) * 64;

    Frag fr;
    #pragma unroll
    for (int mt = 0; mt < 2; mt++)
        #pragma unroll
        for (int nt = 0; nt < 8; nt++)
            #pragma unroll
            for (int j = 0; j < 4; j++) fr.acc[mt][nt][j] = 0.0f;

    load_chunk(sm, 0, h_in, H_, row0, UT, H_, col0, 0, tid);
    CP_COMMIT();
    const int NC = H_ / 32;
    for (int i = 0; i < NC; i++) {
        if (i + 1 < NC) {
            load_chunk(sm, (i + 1) & 1, h_in, H_, row0, UT, H_, col0,
                       (i + 1) * 32, tid);
            CP_COMMIT();
            CP_WAIT1();
        } else {
            CP_WAIT0();
        }
        __syncthreads();
        compute_chunk(sm, i & 1, m0w, n0w, lane, fr);
        __syncthreads();
    }

    // Stage Z tile to shared (overlays the A/B buffers)
    const int q = lane & 3, p = lane >> 2;
    #pragma unroll
    for (int mt = 0; mt < 2; mt++) {
        #pragma unroll
        for (int nt = 0; nt < 8; nt++) {
            int colz = n0w + nt * 8 + 2 * q;
            int rz = m0w + mt * 16 + p;
            *reinterpret_cast<float2*>(&sm[rz * ZS + colz]) =
                *reinterpret_cast<const float2*>(&fr.acc[mt][nt][0]);
            *reinterpret_cast<float2*>(&sm[(rz + 8) * ZS + colz]) =
                *reinterpret_cast<const float2*>(&fr.acc[mt][nt][2]);
        }
    }
    __syncthreads();

    // Gate math: 128 rows x 32 groups per CTA; thread -> (row, group)
    const int g = tid & 31;              // group within tile
    const int g0 = col0 >> 2;            // global hidden-unit base
    #pragma unroll
    for (int it = 0; it < 16; it++) {
        int r = it * 8 + (tid >> 5);
        int b = row0 + r;
        float4 zv = *reinterpret_cast<const float4*>(&sm[r * ZS + 4 * g]);
        float4 zxv = *reinterpret_cast<const float4*>(
            &zx[((size_t)b * T_ + t) * N4H + col0 + 4 * g]);
        float zi = zv.x + zxv.x, zf = zv.y + zxv.y;
        float zg = zv.z + zxv.z, zo = zv.w + zxv.w;
        float ig = sig_fast(zi), fg = sig_fast(zf);
        float gg = tanh_fast(zg), og = sig_fast(zo);
        int cidx = b * H_ + g0 + g;
        float cn = fg * c[cidx] + ig * gg;
        float hn = og * tanh_fast(cn);
        c[cidx] = cn;
        h_out[cidx] = hn;
        out[(size_t)b * T_ * H_ + (size_t)t * H_ + g0 + g] = hn;
    }
}

// ---------------------------------------------------------------------------
// Weight transpose + gate interleave:
//   wt[nn][k] = W[k][n]  where n = (nn>>2) + (nn&3)*Hdim  (nn = 4*unit + gate)
// So column nn of the GEMM output = gate (nn&3) of hidden unit (nn>>2).
// ---------------------------------------------------------------------------
__global__ void transpose_interleave_kernel(const float* __restrict__ in,
                                            float* __restrict__ outp,
                                            int K /*rows of in*/) {
    __shared__ float tile[32][33];
    // Read a 32x32 tile of in[K, 4H] at (y0, x0)
    int x0 = blockIdx.x * 32, y0 = blockIdx.y * 32;
    #pragma unroll
    for (int i = 0; i < 32; i += 8)
        tile[threadIdx.y + i][threadIdx.x] =
            in[(size_t)(y0 + threadIdx.y + i) * N4H + x0 + threadIdx.x];
    __syncthreads();
    // Write transposed with interleave: out row nn = 4*(n%H) + n/H
    #pragma unroll
    for (int i = 0; i < 32; i += 8) {
        int n = x0 + threadIdx.y + i;          // original column
        int nn = ((n & (H_ - 1)) << 2) | (n >> 9);   // n>>9 = gate (H=512)
        int k = y0 + threadIdx.x;
        outp[(size_t)nn * K + k] = tile[threadIdx.x][threadIdx.y + i];
    }
}

// Bias interleave: bias_il[nn] = bias[(nn>>2) + (nn&3)*H]  -- folded into the
// big GEMM by passing an interleaved bias staged in g_wt? Simpler: interleave
// into a small device buffer.
__device__ float g_bias_il[N4H];

__global__ void bias_interleave_kernel(const float* __restrict__ bias,
                                       float* __restrict__ bil) {
    int nn = blockIdx.x * blockDim.x + threadIdx.x;
    if (nn < N4H) bil[nn] = bias[(nn >> 2) + (nn & 3) * H_];
}

__global__ void init_state_kernel(float4* __restrict__ h, float4* __restrict__ c) {
    int idx = blockIdx.x * blockDim.x + threadIdx.x;
    float4 z = {0.f, 0.f, 0.f, 0.f};
    if (idx < B_ * H_ / 4) { h[idx] = z; c[idx] = z; }
}

// ---------------------------------------------------------------------------
// Launch
// ---------------------------------------------------------------------------
extern "C" void kernel_launch(void* const* d_in, const int* in_sizes, int n_in,
                              void* d_out, int out_size)
{
    const float* x    = (const float*)d_in[0];  // [B, T, D]
    const float* W    = (const float*)d_in[1];  // [D, 4H]
    const float* U    = (const float*)d_in[2];  // [H, 4H]
    const float* bias = (const float*)d_in[3];  // [4H]
    float* out = (float*)d_out;                 // [B, T, H]

    float *zx, *h, *c, *wt, *ut, *bil;
    cudaGetSymbolAddress((void**)&zx, g_zx);
    cudaGetSymbolAddress((void**)&h,  g_h);
    cudaGetSymbolAddress((void**)&c,  g_c);
    cudaGetSymbolAddress((void**)&wt, g_wt);
    cudaGetSymbolAddress((void**)&ut, g_ut);
    cudaGetSymbolAddress((void**)&bil, g_bias_il);

    static bool attr_set = false;
    if (!attr_set) {
        cudaFuncSetAttribute(gemm_bias_kernel,
                             cudaFuncAttributeMaxDynamicSharedMemorySize, SM_BYTES);
        cudaFuncSetAttribute(lstm_step_kernel,
                             cudaFuncAttributeMaxDynamicSharedMemorySize, SM_BYTES);
        attr_set = true;
    }

    // Weight prep: transpose + gate-interleave
    {
        dim3 blk(32, 8);
        dim3 grd(N4H / 32, D_ / 32);
        transpose_interleave_kernel<<<grd, blk>>>(W, wt, D_);
        transpose_interleave_kernel<<<grd, blk>>>(U, ut, H_);
        bias_interleave_kernel<<<N4H / 256, 256>>>(bias, bil);
    }

    init_state_kernel<<<(B_ * H_ / 4 + 255) / 256, 256>>>((float4*)h, (float4*)c);

    // Zx = X @ W + bias (all timesteps; rows = b*T + t; cols gate-interleaved)
    {
        dim3 grid(N4H / 128, (B_ * T_) / 128);
        gemm_bias_kernel<<<grid, 256, SM_BYTES>>>(x, D_, wt, D_, zx, N4H, bil);
    }

    // Sequential recurrence with fused gates
    dim3 rgrid(N4H / 128, B_ / 128);
    for (int t = 0; t < T_; t++) {
        lstm_step_kernel<<<rgrid, 256, SM_BYTES>>>(h, ut, zx, t, h, c, out);
    }
}

// round 7
// speedup vs baseline: 2.9674x; 1.0589x over previous
#include <cuda_runtime.h>
#include <math.h>
#include <stdint.h>

#define B_   1024
#define T_   64
#define D_   512
#define H_   512
#define N4H  2048   // 4*H
#define KTOT 1024   // D + H
#define NCTA 128

// ---------------------------------------------------------------------------
// Scratch (device globals: allocation-free per harness rules)
// ---------------------------------------------------------------------------
__device__ float g_wut[(size_t)N4H * KTOT];  // [W;U]^T gate-interleaved [2048,1024]
__device__ float g_h2[2][(size_t)B_ * H_];   // double-buffered hidden state
__device__ float g_bias_il[N4H];             // gate-interleaved bias
__device__ unsigned int g_bar_count;         // grid barrier counter

// ---------------------------------------------------------------------------
// Helpers
// ---------------------------------------------------------------------------
__device__ __forceinline__ uint32_t smem_u32(const void* p) {
    uint32_t a;
    asm("{ .reg .u64 t; cvta.to.shared.u64 t, %1; cvt.u32.u64 %0, t; }"
        : "=r"(a) : "l"(p));
    return a;
}
#define CP_ASYNC16(dst, src) \
    asm volatile("cp.async.cg.shared.global [%0], [%1], 16;" \
                 :: "r"(dst), "l"(src) : "memory")
#define CP_COMMIT() asm volatile("cp.async.commit_group;" ::: "memory")
#define CP_WAIT2()  asm volatile("cp.async.wait_group 2;" ::: "memory")
#define CP_WAIT1()  asm volatile("cp.async.wait_group 1;" ::: "memory")
#define CP_WAIT0()  asm volatile("cp.async.wait_group 0;" ::: "memory")

__device__ __forceinline__ float tanh_fast(float x) {
    float y;
    asm("tanh.approx.f32 %0, %1;" : "=f"(y) : "f"(x));
    return y;
}
__device__ __forceinline__ float sig_fast(float x) {
    return 0.5f * tanh_fast(0.5f * x) + 0.5f;
}

__device__ __forceinline__ void mma_tf32(float* c, const uint32_t* a,
                                         const uint32_t* b) {
    asm volatile(
        "mma.sync.aligned.m16n8k8.row.col.f32.tf32.tf32.f32 "
        "{%0,%1,%2,%3}, {%4,%5,%6,%7}, {%8,%9}, {%0,%1,%2,%3};"
        : "+f"(c[0]), "+f"(c[1]), "+f"(c[2]), "+f"(c[3])
        : "r"(a[0]), "r"(a[1]), "r"(a[2]), "r"(a[3]), "r"(b[0]), "r"(b[1]));
}

// ---------------------------------------------------------------------------
// SMEM geometry (floats):
//   3 pipeline stages, each: A tile [128 x 32] stride 36 @ s*9216,
//                            B tile @ s*9216+4608.  Region = 27648 floats.
//   Z epilogue tile [128 x 128] stride 132 overlays stages (16896 floats).
//   c_tile [128 x 32] @ 27648 (4096 floats, persistent across steps).
// ---------------------------------------------------------------------------
#define TS 36
#define ZS 132
#define STAGE_F 9216
#define CTILE_OFF 27648
#define SM_FLOATS (27648 + 4096)
#define SM_BYTES  (SM_FLOATS * 4)

struct Frag { float acc[2][8][4]; };

// Load one K-chunk into stage buffer s. A source: x slice (k<512) or h (k>=512).
__device__ __forceinline__ void load_chunk_fused(
    float* sm, int s, int chunk, int t,
    const float* __restrict__ x, const float* __restrict__ hr,
    const float* __restrict__ wut, int row0, int col0, int tid)
{
    const int k0 = chunk * 32;
    uint32_t sa = smem_u32(sm + s * STAGE_F);
    uint32_t sb = smem_u32(sm + s * STAGE_F + 4608);
    #pragma unroll
    for (int i = 0; i < 4; i++) {
        int idx = tid + i * 256;          // 0..1023
        int r = idx >> 3, f = idx & 7;
        const float* asrc;
        if (k0 < D_) {
            asrc = &x[((size_t)(row0 + r) * T_ + t) * D_ + k0 + f * 4];
        } else {
            asrc = &hr[(size_t)(row0 + r) * H_ + (k0 - D_) + f * 4];
        }
        CP_ASYNC16(sa + (r * TS + f * 4) * 4, asrc);
        CP_ASYNC16(sb + (r * TS + f * 4) * 4,
                   &wut[(size_t)(col0 + r) * KTOT + k0 + f * 4]);
    }
}

__device__ __forceinline__ void compute_chunk(const float* As, const float* Bs,
                                              int m0w, int n0w, int lane,
                                              Frag& fr) {
    const int q = lane & 3, p = lane >> 2;
    #pragma unroll
    for (int kk = 0; kk < 4; kk++) {
        const int kb = kk * 8;
        uint32_t a[2][4], b[8][2];
        #pragma unroll
        for (int mt = 0; mt < 2; mt++) {
            const float* ap = As + (m0w + mt * 16 + p) * TS + kb + q;
            a[mt][0] = __float_as_uint(ap[0]);
            a[mt][1] = __float_as_uint(ap[8 * TS]);
            a[mt][2] = __float_as_uint(ap[4]);
            a[mt][3] = __float_as_uint(ap[8 * TS + 4]);
        }
        #pragma unroll
        for (int nt = 0; nt < 8; nt++) {
            const float* bp = Bs + (n0w + nt * 8 + p) * TS + kb + q;
            b[nt][0] = __float_as_uint(bp[0]);
            b[nt][1] = __float_as_uint(bp[4]);
        }
        #pragma unroll
        for (int mt = 0; mt < 2; mt++)
            #pragma unroll
            for (int nt = 0; nt < 8; nt++)
                mma_tf32(fr.acc[mt][nt], a[mt], b[nt]);
    }
}

// ---------------------------------------------------------------------------
// Persistent fused LSTM: 128 CTAs, each owns one 128x128 tile of Z for all 64
// steps. Per step: Z = [x_t | h] @ WU^T + bias, then gates, c in SMEM,
// h double-buffered in global, grid barrier between steps.
// ---------------------------------------------------------------------------
__global__ void __launch_bounds__(256, 1)
lstm_persistent_kernel(const float* __restrict__ x,
                       const float* __restrict__ wut,
                       const float* __restrict__ bias_il,
                       float* __restrict__ h0, float* __restrict__ h1,
                       float* __restrict__ out)
{
    extern __shared__ float sm[];
    float* c_tile = sm + CTILE_OFF;

    const int tid = threadIdx.x;
    const int wid = tid >> 5, lane = tid & 31;
    const int cta = blockIdx.x;
    const int row0 = (cta >> 4) * 128;       // batch block
    const int col0 = (cta & 15) * 128;       // gate-col block
    const int m0w = (wid & 3) * 32, n0w = (wid >> 2) * 64;

    // zero persistent c tile
    for (int k = tid; k < 4096; k += 256) c_tile[k] = 0.0f;

    // per-thread epilogue constants
    const int g = tid & 31;                  // hidden-unit group within tile
    const int g0 = col0 >> 2;                // global hidden-unit base
    const float4 bv = *reinterpret_cast<const float4*>(&bias_il[col0 + 4 * g]);
    __syncthreads();

    float* hb[2] = {h0, h1};
    const int NC = KTOT / 32;                // 32 chunks

    for (int t = 0; t < T_; t++) {
        const float* hr = hb[t & 1];
        float* hw = hb[(t + 1) & 1];

        Frag fr;
        #pragma unroll
        for (int mt = 0; mt < 2; mt++)
            #pragma unroll
            for (int nt = 0; nt < 8; nt++)
                #pragma unroll
                for (int j = 0; j < 4; j++) fr.acc[mt][nt][j] = 0.0f;

        load_chunk_fused(sm, 0, 0, t, x, hr, wut, row0, col0, tid);
        CP_COMMIT();
        load_chunk_fused(sm, 1, 1, t, x, hr, wut, row0, col0, tid);
        CP_COMMIT();

        for (int i = 0; i < NC; i++) {
            if (i + 2 < NC) {
                load_chunk_fused(sm, (i + 2) % 3, i + 2, t, x, hr, wut,
                                 row0, col0, tid);
                CP_COMMIT();
                CP_WAIT2();
            } else if (i + 1 < NC) {
                CP_WAIT1();
            } else {
                CP_WAIT0();
            }
            __syncthreads();
            const float* As = sm + (i % 3) * STAGE_F;
            compute_chunk(As, As + 4608, m0w, n0w, lane, fr);
            __syncthreads();
        }

        // Stage Z tile to SMEM (overlays pipeline stages; safe: compute done,
        // next loads happen only after the grid barrier below)
        {
            const int q = lane & 3, p = lane >> 2;
            #pragma unroll
            for (int mt = 0; mt < 2; mt++) {
                #pragma unroll
                for (int nt = 0; nt < 8; nt++) {
                    int colz = n0w + nt * 8 + 2 * q;
                    int rz = m0w + mt * 16 + p;
                    *reinterpret_cast<float2*>(&sm[rz * ZS + colz]) =
                        *reinterpret_cast<const float2*>(&fr.acc[mt][nt][0]);
                    *reinterpret_cast<float2*>(&sm[(rz + 8) * ZS + colz]) =
                        *reinterpret_cast<const float2*>(&fr.acc[mt][nt][2]);
                }
            }
        }
        __syncthreads();

        // Gate math: thread -> (row r, unit group g); cols 4g..4g+3 = (i,f,g,o)
        #pragma unroll
        for (int it = 0; it < 16; it++) {
            int r = it * 8 + wid;
            int b = row0 + r;
            float4 zv = *reinterpret_cast<const float4*>(&sm[r * ZS + 4 * g]);
            float zi = zv.x + bv.x, zf = zv.y + bv.y;
            float zg = zv.z + bv.z, zo = zv.w + bv.w;
            float ig = sig_fast(zi), fg = sig_fast(zf);
            float gg = tanh_fast(zg), og = sig_fast(zo);
            float cold = c_tile[r * 32 + g];
            float cn = fg * cold + ig * gg;
            float hn = og * tanh_fast(cn);
            c_tile[r * 32 + g] = cn;
            hw[(size_t)b * H_ + g0 + g] = hn;
            out[((size_t)b * T_ + t) * H_ + g0 + g] = hn;
        }

        // Grid barrier (release writes of hw, acquire before next step reads)
        if (t + 1 < T_) {
            __syncthreads();
            if (tid == 0) {
                asm volatile("red.release.gpu.global.add.u32 [%0], 1;"
                             :: "l"(&g_bar_count) : "memory");
                unsigned int target = (unsigned)NCTA * (t + 1);
                unsigned int v;
                do {
                    asm volatile("ld.acquire.gpu.global.u32 %0, [%1];"
                                 : "=r"(v) : "l"(&g_bar_count) : "memory");
                    if (v < target) __nanosleep(64);
                } while (v < target);
            }
            __syncthreads();
        }
    }
}

// ---------------------------------------------------------------------------
// Weight prep: wut[nn][ko + k] = in[k][n], nn = 4*(n%H) + n/H (gate interleave)
// ---------------------------------------------------------------------------
__global__ void transpose_interleave_kernel(const float* __restrict__ in,
                                            float* __restrict__ outp,
                                            int ko) {
    __shared__ float tile[32][33];
    int x0 = blockIdx.x * 32, y0 = blockIdx.y * 32;
    #pragma unroll
    for (int i = 0; i < 32; i += 8)
        tile[threadIdx.y + i][threadIdx.x] =
            in[(size_t)(y0 + threadIdx.y + i) * N4H + x0 + threadIdx.x];
    __syncthreads();
    #pragma unroll
    for (int i = 0; i < 32; i += 8) {
        int n = x0 + threadIdx.y + i;
        int nn = ((n & (H_ - 1)) << 2) | (n >> 9);
        int k = y0 + threadIdx.x;
        outp[(size_t)nn * KTOT + ko + k] = tile[threadIdx.x][threadIdx.y + i];
    }
}

__global__ void bias_interleave_kernel(const float* __restrict__ bias,
                                       float* __restrict__ bil) {
    int nn = blockIdx.x * blockDim.x + threadIdx.x;
    if (nn < N4H) bil[nn] = bias[(nn >> 2) + (nn & 3) * H_];
}

__global__ void init_kernel(float4* __restrict__ h0, unsigned int* barc) {
    int idx = blockIdx.x * blockDim.x + threadIdx.x;
    float4 z = {0.f, 0.f, 0.f, 0.f};
    if (idx < B_ * H_ / 4) h0[idx] = z;
    if (idx == 0) *barc = 0;
}

// ---------------------------------------------------------------------------
// Launch
// ---------------------------------------------------------------------------
extern "C" void kernel_launch(void* const* d_in, const int* in_sizes, int n_in,
                              void* d_out, int out_size)
{
    const float* x    = (const float*)d_in[0];  // [B, T, D]
    const float* W    = (const float*)d_in[1];  // [D, 4H]
    const float* U    = (const float*)d_in[2];  // [H, 4H]
    const float* bias = (const float*)d_in[3];  // [4H]
    float* out = (float*)d_out;                 // [B, T, H]

    float *wut, *bil, *h2;
    unsigned int* barc;
    cudaGetSymbolAddress((void**)&wut, g_wut);
    cudaGetSymbolAddress((void**)&bil, g_bias_il);
    cudaGetSymbolAddress((void**)&h2,  g_h2);
    cudaGetSymbolAddress((void**)&barc, g_bar_count);
    float* h0 = h2;
    float* h1 = h2 + (size_t)B_ * H_;

    cudaFuncSetAttribute(lstm_persistent_kernel,
                         cudaFuncAttributeMaxDynamicSharedMemorySize, SM_BYTES);

    // Prep: pack [W;U]^T gate-interleaved, bias, zero h0, reset barrier
    {
        dim3 blk(32, 8);
        dim3 grdW(N4H / 32, D_ / 32);
        dim3 grdU(N4H / 32, H_ / 32);
        transpose_interleave_kernel<<<grdW, blk>>>(W, wut, 0);
        transpose_interleave_kernel<<<grdU, blk>>>(U, wut, D_);
        bias_interleave_kernel<<<N4H / 256, 256>>>(bias, bil);
        init_kernel<<<(B_ * H_ / 4 + 255) / 256, 256>>>((float4*)h0, barc);
    }

    // One persistent kernel: all 64 timesteps fused
    lstm_persistent_kernel<<<NCTA, 256, SM_BYTES>>>(x, wut, bil, h0, h1, out);
}

// round 8
// speedup vs baseline: 5.3959x; 1.8184x over previous
#include <cuda_runtime.h>
#include <cuda_fp16.h>
#include <math.h>
#include <stdint.h>

#define B_   1024
#define T_   64
#define D_   512
#define H_   512
#define N4H  2048   // 4*H
#define KTOT 1024   // D + H
#define NCTA 128

// ---------------------------------------------------------------------------
// Scratch (device globals: allocation-free per harness rules)
// ---------------------------------------------------------------------------
__device__ __half g_wuth[(size_t)N4H * KTOT];   // [W;U]^T gate-interleaved, fp16
__device__ __half g_xh[(size_t)B_ * T_ * D_];   // x converted to fp16
__device__ __half g_h2h[2][(size_t)B_ * H_];    // double-buffered hidden (fp16)
__device__ float  g_bias_il[N4H];               // gate-interleaved bias (fp32)
__device__ unsigned int g_bar_count;            // grid barrier counter

// ---------------------------------------------------------------------------
// Helpers
// ---------------------------------------------------------------------------
__device__ __forceinline__ uint32_t smem_u32(const void* p) {
    uint32_t a;
    asm("{ .reg .u64 t; cvta.to.shared.u64 t, %1; cvt.u32.u64 %0, t; }"
        : "=r"(a) : "l"(p));
    return a;
}
#define CP_ASYNC16(dst, src) \
    asm volatile("cp.async.cg.shared.global [%0], [%1], 16;" \
                 :: "r"(dst), "l"(src) : "memory")
#define CP_COMMIT() asm volatile("cp.async.commit_group;" ::: "memory")
#define CP_WAIT1()  asm volatile("cp.async.wait_group 1;" ::: "memory")
#define CP_WAIT0()  asm volatile("cp.async.wait_group 0;" ::: "memory")

#define LDSM_X4(r0, r1, r2, r3, addr) \
    asm volatile("ldmatrix.sync.aligned.m8n8.x4.shared.b16 {%0,%1,%2,%3}, [%4];" \
                 : "=r"(r0), "=r"(r1), "=r"(r2), "=r"(r3) : "r"(addr))

__device__ __forceinline__ float tanh_fast(float x) {
    float y;
    asm("tanh.approx.f32 %0, %1;" : "=f"(y) : "f"(x));
    return y;
}
__device__ __forceinline__ float sig_fast(float x) {
    return 0.5f * tanh_fast(0.5f * x) + 0.5f;
}

// m16n8k16 fp16 -> fp32 accumulate
__device__ __forceinline__ void mma_f16(float* c, const uint32_t* a,
                                        const uint32_t* b) {
    asm volatile(
        "mma.sync.aligned.m16n8k16.row.col.f32.f16.f16.f32 "
        "{%0,%1,%2,%3}, {%4,%5,%6,%7}, {%8,%9}, {%0,%1,%2,%3};"
        : "+f"(c[0]), "+f"(c[1]), "+f"(c[2]), "+f"(c[3])
        : "r"(a[0]), "r"(a[1]), "r"(a[2]), "r"(a[3]), "r"(b[0]), "r"(b[1]));
}

// ---------------------------------------------------------------------------
// SMEM geometry (bytes):
//   3 stages, each: A [128 rows x 64 halves] stride 72 halves (144B) = 18432B
//                   B same, at +18432.   Stage = 36864B, stages at s*36864.
//   Z epilogue tile [128 x 132] fp32 overlays stages 0-1 (67584B).
//   c_tile [128 x 32] fp32 at byte 110592 (16384B).  Total = 126976B.
// ---------------------------------------------------------------------------
#define AS_B      144          // row stride in bytes (72 halves)
#define STAGE_B   36864
#define B_OFF_B   18432
#define ZS        132          // Z row stride (floats)
#define CTILE_F   27648        // c_tile offset (floats)
#define SM_BYTES  126976

struct Frag { float acc[2][8][4]; };

// Load one K-chunk (64 halves) into stage s.
__device__ __forceinline__ void load_chunk(
    uint32_t smb, int s, int chunk, int t,
    const __half* __restrict__ xh, const __half* __restrict__ hr,
    const __half* __restrict__ wuth, int row0, int col0, int tid)
{
    const int k0 = chunk * 64;
    const uint32_t sa = smb + s * STAGE_B;
    const uint32_t sb = sa + B_OFF_B;
    #pragma unroll
    for (int i = 0; i < 4; i++) {
        int idx = tid + i * 256;          // 0..1023 = 128 rows x 8 groups
        int r = idx >> 3, f = idx & 7;
        const __half* asrc;
        if (k0 < D_) {
            asrc = &xh[((size_t)(row0 + r) * T_ + t) * D_ + k0 + f * 8];
        } else {
            asrc = &hr[(size_t)(row0 + r) * H_ + (k0 - D_) + f * 8];
        }
        CP_ASYNC16(sa + r * AS_B + f * 16, asrc);
        CP_ASYNC16(sb + r * AS_B + f * 16,
                   &wuth[(size_t)(col0 + r) * KTOT + k0 + f * 8]);
    }
}

// Compute one 64-k chunk from stage s. Warp tile 32x64.
__device__ __forceinline__ void compute_chunk(uint32_t smb, int s,
                                              int m0w, int n0w, int lane,
                                              Frag& fr) {
    const uint32_t aS = smb + s * STAGE_B;
    const uint32_t bS = aS + B_OFF_B;
    const int j = lane >> 3, lr = lane & 7;
    const int jr = (j & 1) << 3;          // +8 rows for tiles 1,3
    const int jk = (j >> 1) << 4;         // +8 halves (16B) for tiles 2,3
    const int jr2 = (j >> 1) << 3;        // B: +8 rows for tiles 2,3
    const int jk2 = (j & 1) << 4;         // B: +8 halves for tiles 1,3

    uint32_t a_off[2], b_off[4];
    #pragma unroll
    for (int mt = 0; mt < 2; mt++)
        a_off[mt] = aS + (m0w + mt * 16 + jr + lr) * AS_B + jk;
    #pragma unroll
    for (int np = 0; np < 4; np++)
        b_off[np] = bS + (n0w + np * 16 + jr2 + lr) * AS_B + jk2;

    #pragma unroll
    for (int kk = 0; kk < 4; kk++) {
        const int kb = kk * 32;           // 16 halves = 32 bytes per k16
        uint32_t a[2][4], b[8][2];
        LDSM_X4(a[0][0], a[0][1], a[0][2], a[0][3], a_off[0] + kb);
        LDSM_X4(a[1][0], a[1][1], a[1][2], a[1][3], a_off[1] + kb);
        #pragma unroll
        for (int np = 0; np < 4; np++)
            LDSM_X4(b[2 * np][0], b[2 * np][1], b[2 * np + 1][0],
                    b[2 * np + 1][1], b_off[np] + kb);
        #pragma unroll
        for (int mt = 0; mt < 2; mt++)
            #pragma unroll
            for (int nt = 0; nt < 8; nt++)
                mma_f16(fr.acc[mt][nt], a[mt], b[nt]);
    }
}

// ---------------------------------------------------------------------------
// Persistent fused LSTM: 128 CTAs, tile 128 (batch) x 128 (gate cols).
// ---------------------------------------------------------------------------
__global__ void __launch_bounds__(256, 1)
lstm_persistent_kernel(const __half* __restrict__ xh,
                       const __half* __restrict__ wuth,
                       const float* __restrict__ bias_il,
                       __half* __restrict__ h0, __half* __restrict__ h1,
                       float* __restrict__ out)
{
    extern __shared__ float sm[];
    const uint32_t smb = smem_u32(sm);
    float* c_tile = sm + CTILE_F;

    const int tid = threadIdx.x;
    const int wid = tid >> 5, lane = tid & 31;
    const int cta = blockIdx.x;
    const int row0 = (cta >> 4) * 128;       // batch block
    const int col0 = (cta & 15) * 128;       // gate-col block
    const int m0w = (wid & 3) * 32, n0w = (wid >> 2) * 64;

    for (int k = tid; k < 4096; k += 256) c_tile[k] = 0.0f;

    const int g = tid & 31;                  // hidden-unit group within tile
    const int g0 = col0 >> 2;                // global hidden-unit base
    const float4 bv = *reinterpret_cast<const float4*>(&bias_il[col0 + 4 * g]);
    __syncthreads();

    __half* hb[2] = {h0, h1};
    const int NC = KTOT / 64;                // 16 chunks

    for (int t = 0; t < T_; t++) {
        const __half* hr = hb[t & 1];
        __half* hw = hb[(t + 1) & 1];

        Frag fr;
        #pragma unroll
        for (int mt = 0; mt < 2; mt++)
            #pragma unroll
            for (int nt = 0; nt < 8; nt++)
                #pragma unroll
                for (int jj = 0; jj < 4; jj++) fr.acc[mt][nt][jj] = 0.0f;

        load_chunk(smb, 0, 0, t, xh, hr, wuth, row0, col0, tid);
        CP_COMMIT();
        load_chunk(smb, 1, 1, t, xh, hr, wuth, row0, col0, tid);
        CP_COMMIT();

        for (int i = 0; i < NC; i++) {
            if (i < NC - 1) { CP_WAIT1(); } else { CP_WAIT0(); }
            __syncthreads();
            if (i + 2 < NC) {
                load_chunk(smb, (i + 2) % 3, i + 2, t, xh, hr, wuth,
                           row0, col0, tid);
                CP_COMMIT();
            }
            compute_chunk(smb, i % 3, m0w, n0w, lane, fr);
        }
        __syncthreads();   // all warps done computing before Z overlays stages

        // Stage Z tile to SMEM
        {
            const int q = lane & 3, p = lane >> 2;
            #pragma unroll
            for (int mt = 0; mt < 2; mt++) {
                #pragma unroll
                for (int nt = 0; nt < 8; nt++) {
                    int colz = n0w + nt * 8 + 2 * q;
                    int rz = m0w + mt * 16 + p;
                    *reinterpret_cast<float2*>(&sm[rz * ZS + colz]) =
                        *reinterpret_cast<const float2*>(&fr.acc[mt][nt][0]);
                    *reinterpret_cast<float2*>(&sm[(rz + 8) * ZS + colz]) =
                        *reinterpret_cast<const float2*>(&fr.acc[mt][nt][2]);
                }
            }
        }
        __syncthreads();

        // Gate math: thread -> (row r, unit group g); cols 4g..4g+3 = (i,f,g,o)
        #pragma unroll
        for (int it = 0; it < 16; it++) {
            int r = it * 8 + wid;
            int b = row0 + r;
            float4 zv = *reinterpret_cast<const float4*>(&sm[r * ZS + 4 * g]);
            float zi = zv.x + bv.x, zf = zv.y + bv.y;
            float zg = zv.z + bv.z, zo = zv.w + bv.w;
            float ig = sig_fast(zi), fg = sig_fast(zf);
            float gg = tanh_fast(zg), og = sig_fast(zo);
            float cold = c_tile[r * 32 + g];
            float cn = fg * cold + ig * gg;
            float hn = og * tanh_fast(cn);
            c_tile[r * 32 + g] = cn;
            hw[(size_t)b * H_ + g0 + g] = __float2half(hn);
            out[((size_t)b * T_ + t) * H_ + g0 + g] = hn;
        }

        // Grid barrier
        if (t + 1 < T_) {
            __syncthreads();
            if (tid == 0) {
                asm volatile("red.release.gpu.global.add.u32 [%0], 1;"
                             :: "l"(&g_bar_count) : "memory");
                unsigned int target = (unsigned)NCTA * (t + 1);
                unsigned int v;
                do {
                    asm volatile("ld.acquire.gpu.global.u32 %0, [%1];"
                                 : "=r"(v) : "l"(&g_bar_count) : "memory");
                    if (v < target) __nanosleep(64);
                } while (v < target);
            }
            __syncthreads();
        }
    }
}

// ---------------------------------------------------------------------------
// Prep kernels
// ---------------------------------------------------------------------------
// Transpose + gate-interleave + fp16 convert: wuth[nn][ko+k] = half(in[k][n])
__global__ void transpose_interleave_h_kernel(const float* __restrict__ in,
                                              __half* __restrict__ outp,
                                              int ko) {
    __shared__ float tile[32][33];
    int x0 = blockIdx.x * 32, y0 = blockIdx.y * 32;
    #pragma unroll
    for (int i = 0; i < 32; i += 8)
        tile[threadIdx.y + i][threadIdx.x] =
            in[(size_t)(y0 + threadIdx.y + i) * N4H + x0 + threadIdx.x];
    __syncthreads();
    #pragma unroll
    for (int i = 0; i < 32; i += 8) {
        int n = x0 + threadIdx.y + i;
        int nn = ((n & (H_ - 1)) << 2) | (n >> 9);
        int k = y0 + threadIdx.x;
        outp[(size_t)nn * KTOT + ko + k] =
            __float2half(tile[threadIdx.x][threadIdx.y + i]);
    }
}

// Convert x (fp32) -> fp16, 8 elements/thread
__global__ void convert_x_kernel(const float4* __restrict__ x,
                                 uint4* __restrict__ xh) {
    size_t i = (size_t)blockIdx.x * blockDim.x + threadIdx.x;
    if (i >= (size_t)B_ * T_ * D_ / 8) return;
    float4 v0 = x[2 * i], v1 = x[2 * i + 1];
    __half2 h0 = __floats2half2_rn(v0.x, v0.y);
    __half2 h1 = __floats2half2_rn(v0.z, v0.w);
    __half2 h2 = __floats2half2_rn(v1.x, v1.y);
    __half2 h3 = __floats2half2_rn(v1.z, v1.w);
    uint4 o;
    o.x = *reinterpret_cast<uint32_t*>(&h0);
    o.y = *reinterpret_cast<uint32_t*>(&h1);
    o.z = *reinterpret_cast<uint32_t*>(&h2);
    o.w = *reinterpret_cast<uint32_t*>(&h3);
    xh[i] = o;
}

__global__ void bias_interleave_kernel(const float* __restrict__ bias,
                                       float* __restrict__ bil) {
    int nn = blockIdx.x * blockDim.x + threadIdx.x;
    if (nn < N4H) bil[nn] = bias[(nn >> 2) + (nn & 3) * H_];
}

__global__ void init_kernel(uint4* __restrict__ h0, unsigned int* barc) {
    int idx = blockIdx.x * blockDim.x + threadIdx.x;
    uint4 z = {0u, 0u, 0u, 0u};
    if (idx < B_ * H_ / 8) h0[idx] = z;     // fp16 zeros
    if (idx == 0) *barc = 0;
}

// ---------------------------------------------------------------------------
// Launch
// ---------------------------------------------------------------------------
extern "C" void kernel_launch(void* const* d_in, const int* in_sizes, int n_in,
                              void* d_out, int out_size)
{
    const float* x    = (const float*)d_in[0];  // [B, T, D]
    const float* W    = (const float*)d_in[1];  // [D, 4H]
    const float* U    = (const float*)d_in[2];  // [H, 4H]
    const float* bias = (const float*)d_in[3];  // [4H]
    float* out = (float*)d_out;                 // [B, T, H]

    __half *wuth, *xh, *h2h;
    float* bil;
    unsigned int* barc;
    cudaGetSymbolAddress((void**)&wuth, g_wuth);
    cudaGetSymbolAddress((void**)&xh,   g_xh);
    cudaGetSymbolAddress((void**)&h2h,  g_h2h);
    cudaGetSymbolAddress((void**)&bil,  g_bias_il);
    cudaGetSymbolAddress((void**)&barc, g_bar_count);
    __half* h0 = h2h;
    __half* h1 = h2h + (size_t)B_ * H_;

    cudaFuncSetAttribute(lstm_persistent_kernel,
                         cudaFuncAttributeMaxDynamicSharedMemorySize, SM_BYTES);

    // Prep
    {
        dim3 blk(32, 8);
        dim3 grdW(N4H / 32, D_ / 32);
        dim3 grdU(N4H / 32, H_ / 32);
        transpose_interleave_h_kernel<<<grdW, blk>>>(W, wuth, 0);
        transpose_interleave_h_kernel<<<grdU, blk>>>(U, wuth, D_);
        bias_interleave_kernel<<<N4H / 256, 256>>>(bias, bil);
        size_t nx8 = (size_t)B_ * T_ * D_ / 8;
        convert_x_kernel<<<(unsigned)((nx8 + 255) / 256), 256>>>(
            (const float4*)x, (uint4*)xh);
        init_kernel<<<(B_ * H_ / 8 + 255) / 256, 256>>>((uint4*)h0, barc);
    }

    // One persistent kernel: all 64 timesteps fused
    lstm_persistent_kernel<<<NCTA, 256, SM_BYTES>>>(xh, wuth, bil, h0, h1, out);
}